// round 3
// baseline (speedup 1.0000x reference)
#include <cuda_runtime.h>
#include <cstdint>

// ---------------- problem constants ----------------
#define BATCH   4096
#define FRAME   267
#define LATENT  32
#define HIDDEN  256
#define GATE_H  64
#define EXPERTS 6
#define IN0     (LATENT + FRAME)    // 299
#define IN1     (LATENT + HIDDEN)   // 288
#define OUTD    FRAME               // 267

#define OFF_MU  (BATCH * OUTD)
#define OFF_LV  (OFF_MU + BATCH * LATENT)

// ---------------- scratch (allocation-free) ----------------
__device__ float g_h1[BATCH * HIDDEN];
__device__ float g_h2[BATCH * HIDDEN];
__device__ float g_zbuf[BATCH * LATENT];
__device__ float g_g1[BATCH * GATE_H];
__device__ float g_coef[BATCH * EXPERTS];
__device__ float g_d1[BATCH * HIDDEN];
__device__ float g_d2[BATCH * HIDDEN];

__device__ __forceinline__ float elu1(float x) { return x > 0.f ? x : expm1f(x); }

__device__ __forceinline__ float tf32r(float x) {
    float y;
    asm("cvt.rna.tf32.f32 %0, %1;" : "=f"(y) : "f"(x));
    return y;
}

// ============================================================
// Pipelined tf32 mma GEMM, permuted smem for LDS.128 fragments.
//   C[m,n] = act( Afold[m,:] @ Wflat[:,n] + biasblend )
//   Afold[m, e*DIN+i] = (i<K0 ? A0[m,i] : A1[m,i-K0]) * (E>1 ? coeff[m,e] : 1)
// Tile 64x64xBK32, 256 threads, 8 warps (4m x 2n), warp tile 16x32.
// Permutation: element k of a row stored at p = (k&3)*8 + (k>>2), so the
// 8 values a thread with tg=k&3 needs (k = tg+4j, j=0..7) are contiguous.
// DUAL mode: mu/lv packed in one 64-wide tile; z computed in epilogue.
// ============================================================
#define BK 32

template<int N_, int K0_, int DIN_, int E_, bool DUAL_, int ACT_>
__global__ __launch_bounds__(256) void mma_gemm(
    const float* __restrict__ A0, int lda0,
    const float* __restrict__ A1, int lda1,
    const float* __restrict__ coeff,
    const float* __restrict__ W,  const float* __restrict__ bias,
    const float* __restrict__ W2, const float* __restrict__ bias2,
    float* __restrict__ C, int ldc, float* __restrict__ C2,
    const float* __restrict__ epsv, float* __restrict__ zout)
{
    constexpr int Ktot = E_ * DIN_;
    __shared__ __align__(16) float Asp[64][36];
    __shared__ __align__(16) float Bsp[64][36];

    const int tid  = threadIdx.x;
    const int lane = tid & 31;
    const int wid  = tid >> 5;
    const int wm16 = (wid >> 1) << 4;   // 0,16,32,48
    const int wn32 = (wid & 1) << 5;    // 0,32
    const int gid  = lane >> 2;
    const int tg   = lane & 3;

    const int bm_ = blockIdx.y * 64;
    const int bn_ = blockIdx.x * 64;

    // producer mappings
    const int amL = tid >> 3;            // 0..31
    const int akq = (tid & 7) << 2;      // 0..28
    const int aj  = tid & 7;             // = akq>>2
    const int bkL = tid >> 4;            // 0..15
    const int bnb = (tid & 15) << 2;     // 0..60

    float avv[2][4];                     // staged A (post coeff-fold)
    float bvv[2][4];                     // staged B

    // ---- LDG stage (global -> regs) ----
    auto ldgA = [&](int kt) {
        #pragma unroll
        for (int half = 0; half < 2; half++) {
            const int m = bm_ + amL + half * 32;
            #pragma unroll
            for (int j = 0; j < 4; j++) {
                const int ig = kt + akq + j;
                float val = 0.f;
                if ((Ktot % BK == 0) || ig < Ktot) {
                    int e, i;
                    if (E_ == 1) { e = 0; i = ig; }
                    else { e = ig / DIN_; i = ig - e * DIN_; }
                    val = (i < K0_) ? __ldg(&A0[m * lda0 + i])
                                    : __ldg(&A1[m * lda1 + (i - K0_)]);
                    if (E_ > 1) val *= __ldg(&coeff[m * E_ + e]);
                }
                avv[half][j] = val;
            }
        }
    };
    auto ldgB = [&](int kt) {
        #pragma unroll
        for (int half = 0; half < 2; half++) {
            const int kg = kt + bkL + half * 16;
            const bool kok = (Ktot % BK == 0) || (kg < Ktot);
            #pragma unroll
            for (int j = 0; j < 4; j++) {
                float val = 0.f;
                if (kok) {
                    if (DUAL_) {
                        const int nl = bnb + j;
                        val = (nl < 32) ? __ldg(&W [kg * 32 + nl])
                                        : __ldg(&W2[kg * 32 + (nl - 32)]);
                    } else {
                        const int n = bn_ + bnb + j;
                        if ((N_ % 64) == 0 || n < N_) val = __ldg(&W[kg * N_ + n]);
                    }
                }
                bvv[half][j] = val;
            }
        }
    };
    // ---- STS stage (regs -> permuted smem, tf32 rounded) ----
    auto sts = [&]() {
        #pragma unroll
        for (int half = 0; half < 2; half++) {
            const int mL = amL + half * 32;
            #pragma unroll
            for (int j = 0; j < 4; j++)
                Asp[mL][j * 8 + aj] = tf32r(avv[half][j]);
        }
        #pragma unroll
        for (int half = 0; half < 2; half++) {
            const int kL = bkL + half * 16;
            const int pB = (kL & 3) * 8 + (kL >> 2);
            #pragma unroll
            for (int j = 0; j < 4; j++)
                Bsp[bnb + j][pB] = tf32r(bvv[half][j]);
        }
    };

    float acc[4][4] = {};

    ldgA(0); ldgB(0);
    for (int kt = 0; kt < Ktot; kt += BK) {
        sts();
        __syncthreads();
        if (kt + BK < Ktot) { ldgA(kt + BK); ldgB(kt + BK); }

        // fragment loads: 2x float4 per row/col cover all 4 k-steps
        float al[8], ah[8];
        {
            const float4* r0 = (const float4*)&Asp[wm16 + gid][0];
            const float4* r1 = (const float4*)&Asp[wm16 + gid + 8][0];
            float4 t0 = r0[tg * 2], t1 = r0[tg * 2 + 1];
            float4 u0 = r1[tg * 2], u1 = r1[tg * 2 + 1];
            al[0]=t0.x; al[1]=t0.y; al[2]=t0.z; al[3]=t0.w;
            al[4]=t1.x; al[5]=t1.y; al[6]=t1.z; al[7]=t1.w;
            ah[0]=u0.x; ah[1]=u0.y; ah[2]=u0.z; ah[3]=u0.w;
            ah[4]=u1.x; ah[5]=u1.y; ah[6]=u1.z; ah[7]=u1.w;
        }
        float bv[4][8];
        #pragma unroll
        for (int t = 0; t < 4; t++) {
            const float4* rc = (const float4*)&Bsp[wn32 + (t << 3) + gid][0];
            float4 v0 = rc[tg * 2], v1 = rc[tg * 2 + 1];
            bv[t][0]=v0.x; bv[t][1]=v0.y; bv[t][2]=v0.z; bv[t][3]=v0.w;
            bv[t][4]=v1.x; bv[t][5]=v1.y; bv[t][6]=v1.z; bv[t][7]=v1.w;
        }
        #pragma unroll
        for (int ks = 0; ks < 4; ks++) {
            const int j0 = 2 * ks, j1 = j0 + 1;
            uint32_t a0 = __float_as_uint(al[j0]);
            uint32_t a1 = __float_as_uint(ah[j0]);
            uint32_t a2 = __float_as_uint(al[j1]);
            uint32_t a3 = __float_as_uint(ah[j1]);
            #pragma unroll
            for (int t = 0; t < 4; t++) {
                uint32_t b0 = __float_as_uint(bv[t][j0]);
                uint32_t b1 = __float_as_uint(bv[t][j1]);
                asm volatile(
                    "mma.sync.aligned.m16n8k8.row.col.f32.tf32.tf32.f32 "
                    "{%0,%1,%2,%3}, {%4,%5,%6,%7}, {%8,%9}, {%0,%1,%2,%3};\n"
                    : "+f"(acc[t][0]), "+f"(acc[t][1]),
                      "+f"(acc[t][2]), "+f"(acc[t][3])
                    : "r"(a0), "r"(a1), "r"(a2), "r"(a3), "r"(b0), "r"(b1));
            }
        }
        __syncthreads();
    }

    // ---- epilogue ----
    const int r0 = bm_ + wm16 + gid;
    const int r1 = r0 + 8;
    float cf0[E_ > 1 ? E_ : 1], cf1[E_ > 1 ? E_ : 1];
    if (E_ > 1) {
        #pragma unroll
        for (int e = 0; e < E_; e++) {
            cf0[e] = coeff[r0 * E_ + e];
            cf1[e] = coeff[r1 * E_ + e];
        }
    }

    float* muS = &Asp[0][0];   // reuse as [64][33] (DUAL only)
    float* lvS = &Bsp[0][0];

    #pragma unroll
    for (int t = 0; t < 4; t++) {
        #pragma unroll
        for (int q = 0; q < 4; q++) {
            const int r  = (q < 2) ? r0 : r1;
            const float* cf = (q < 2) ? cf0 : cf1;
            const int colL = wn32 + (t << 3) + (tg << 1) + (q & 1);
            float v = acc[t][q];
            if (DUAL_) {
                const int rL = r - bm_;
                if (colL < 32) {
                    v += bias[colL];
                    C[r * 32 + colL] = v;
                    muS[rL * 33 + colL] = v;
                } else {
                    v += bias2[colL - 32];
                    C2[r * 32 + (colL - 32)] = v;
                    lvS[rL * 33 + (colL - 32)] = v;
                }
            } else {
                const int cG = bn_ + colL;
                if ((N_ % 64) == 0 || cG < N_) {
                    float bb;
                    if (E_ > 1) {
                        bb = 0.f;
                        #pragma unroll
                        for (int e = 0; e < E_; e++)
                            bb = fmaf(cf[e], __ldg(&bias[e * N_ + cG]), bb);
                    } else {
                        bb = bias[cG];
                    }
                    v += bb;
                    if (ACT_ == 1) v = elu1(v);
                    C[r * ldc + cG] = v;
                }
            }
        }
    }

    if (DUAL_) {   // fused reparameterization: z = mu + eps*exp(0.5*lv)
        __syncthreads();
        #pragma unroll
        for (int e = tid; e < 64 * 32; e += 256) {
            const int rL = e >> 5, cl = e & 31;
            const int r = bm_ + rL;
            const float m_ = muS[rL * 33 + cl];
            const float l_ = lvS[rL * 33 + cl];
            zout[r * 32 + cl] = fmaf(epsv[r * 32 + cl], expf(0.5f * l_), m_);
        }
    }
}

// ---------------- fused gate layer1 + layer2 + softmax ----------------
// block: 256 threads, 32 rows. gw1 (64x64) + gw2 (64x6) resident in smem.
__global__ __launch_bounds__(256) void gate12_softmax(
    const float* __restrict__ g1, const float* __restrict__ w1,
    const float* __restrict__ b1, const float* __restrict__ w2,
    const float* __restrict__ b2, float* __restrict__ coeff)
{
    __shared__ float w1s[64][65];
    __shared__ float w2s[64][8];
    __shared__ float b1s[64];
    __shared__ float g1s[32][64];
    __shared__ float g2s[32][65];

    const int tid = threadIdx.x;
    const int row0 = blockIdx.x * 32;

    for (int i = tid; i < 64 * 64; i += 256) w1s[i >> 6][i & 63] = w1[i];
    for (int i = tid; i < 64 * EXPERTS; i += 256) w2s[i / EXPERTS][i % EXPERTS] = w2[i];
    if (tid < 64) b1s[tid] = b1[tid];
    for (int i = tid; i < 32 * 64; i += 256)
        g1s[i >> 6][i & 63] = g1[(row0 + (i >> 6)) * GATE_H + (i & 63)];
    __syncthreads();

    // layer 1: each thread -> 8 outputs of one row
    const int ri = tid >> 3;
    const int c0 = (tid & 7) << 3;
    float acc[8];
    #pragma unroll
    for (int c = 0; c < 8; c++) acc[c] = b1s[c0 + c];
    #pragma unroll
    for (int k = 0; k < 64; k++) {
        const float gv = g1s[ri][k];
        #pragma unroll
        for (int c = 0; c < 8; c++) acc[c] = fmaf(gv, w1s[k][c0 + c], acc[c]);
    }
    #pragma unroll
    for (int c = 0; c < 8; c++) g2s[ri][c0 + c] = elu1(acc[c]);
    __syncthreads();

    // layer 2 + softmax: one thread per row
    if (tid < 32) {
        float lg[EXPERTS];
        #pragma unroll
        for (int e = 0; e < EXPERTS; e++) lg[e] = b2[e];
        #pragma unroll
        for (int k = 0; k < 64; k++) {
            const float gv = g2s[tid][k];
            #pragma unroll
            for (int e = 0; e < EXPERTS; e++) lg[e] = fmaf(gv, w2s[k][e], lg[e]);
        }
        float mx = lg[0];
        #pragma unroll
        for (int e = 1; e < EXPERTS; e++) mx = fmaxf(mx, lg[e]);
        float s = 0.f;
        #pragma unroll
        for (int e = 0; e < EXPERTS; e++) { lg[e] = expf(lg[e] - mx); s += lg[e]; }
        const float inv = 1.f / s;
        #pragma unroll
        for (int e = 0; e < EXPERTS; e++)
            coeff[(row0 + tid) * EXPERTS + e] = lg[e] * inv;
    }
}

// ---------------- launch ----------------
extern "C" void kernel_launch(void* const* d_in, const int* in_sizes, int n_in,
                              void* d_out, int out_size)
{
    const float* x       = (const float*)d_in[0];
    const float* c       = (const float*)d_in[1];
    const float* eps     = (const float*)d_in[2];
    const float* enc_w1  = (const float*)d_in[3];
    const float* enc_b1  = (const float*)d_in[4];
    const float* enc_w2  = (const float*)d_in[5];
    const float* enc_b2  = (const float*)d_in[6];
    const float* enc_wmu = (const float*)d_in[7];
    const float* enc_bmu = (const float*)d_in[8];
    const float* enc_wlv = (const float*)d_in[9];
    const float* enc_blv = (const float*)d_in[10];
    const float* gw0     = (const float*)d_in[11];
    const float* gb0     = (const float*)d_in[12];
    const float* gw1     = (const float*)d_in[13];
    const float* gb1     = (const float*)d_in[14];
    const float* gw2     = (const float*)d_in[15];
    const float* gb2     = (const float*)d_in[16];
    const float* w0      = (const float*)d_in[17];
    const float* b0      = (const float*)d_in[18];
    const float* w1      = (const float*)d_in[19];
    const float* b1      = (const float*)d_in[20];
    const float* w2      = (const float*)d_in[21];
    const float* b2      = (const float*)d_in[22];
    float* out = (float*)d_out;

    float *h1, *h2, *z, *g1, *coef, *d1, *d2;
    cudaGetSymbolAddress((void**)&h1,   g_h1);
    cudaGetSymbolAddress((void**)&h2,   g_h2);
    cudaGetSymbolAddress((void**)&z,    g_zbuf);
    cudaGetSymbolAddress((void**)&g1,   g_g1);
    cudaGetSymbolAddress((void**)&coef, g_coef);
    cudaGetSymbolAddress((void**)&d1,   g_d1);
    cudaGetSymbolAddress((void**)&d2,   g_d2);

    const dim3 blk(256);
    const dim3 gridH(HIDDEN / 64, BATCH / 64);              // (4, 64)
    const dim3 grid1(1, BATCH / 64);                        // (1, 64)
    const dim3 gridO((OUTD + 63) / 64, BATCH / 64);         // (5, 64)

    // encoder layer 1: h1 = elu([x, c] @ enc_w1 + b1)   Ktot=534
    mma_gemm<HIDDEN, FRAME, 2*FRAME, 1, false, 1><<<gridH, blk>>>(
        x, FRAME, c, FRAME, nullptr, enc_w1, enc_b1, nullptr, nullptr,
        h1, HIDDEN, nullptr, nullptr, nullptr);
    // encoder layer 2: h2 = elu([x, h1] @ enc_w2 + b2)  Ktot=523
    mma_gemm<HIDDEN, FRAME, FRAME+HIDDEN, 1, false, 1><<<gridH, blk>>>(
        x, FRAME, h1, HIDDEN, nullptr, enc_w2, enc_b2, nullptr, nullptr,
        h2, HIDDEN, nullptr, nullptr, nullptr);
    // mu + logvar (dual) with fused z = mu + eps*exp(0.5*lv)
    mma_gemm<64, FRAME, FRAME+HIDDEN, 1, true, 0><<<grid1, blk>>>(
        x, FRAME, h2, HIDDEN, nullptr, enc_wmu, enc_bmu, enc_wlv, enc_blv,
        out + OFF_MU, LATENT, out + OFF_LV, eps, z);
    // gate layer 0: g1 = elu([z, c] @ gw0 + gb0)  Ktot=299
    mma_gemm<GATE_H, LATENT, IN0, 1, false, 1><<<grid1, blk>>>(
        z, LATENT, c, FRAME, nullptr, gw0, gb0, nullptr, nullptr,
        g1, GATE_H, nullptr, nullptr, nullptr);
    // gate layers 1+2 + softmax (fused)
    gate12_softmax<<<BATCH / 32, blk>>>(g1, gw1, gb1, gw2, gb2, coef);

    // MoE decoder layer 0: Ktot = 6*299 = 1794
    mma_gemm<HIDDEN, LATENT, IN0, EXPERTS, false, 1><<<gridH, blk>>>(
        z, LATENT, c, FRAME, coef, w0, b0, nullptr, nullptr,
        d1, HIDDEN, nullptr, nullptr, nullptr);
    // MoE decoder layer 1: Ktot = 6*288 = 1728
    mma_gemm<HIDDEN, LATENT, IN1, EXPERTS, false, 1><<<gridH, blk>>>(
        z, LATENT, d1, HIDDEN, coef, w1, b1, nullptr, nullptr,
        d2, HIDDEN, nullptr, nullptr, nullptr);
    // MoE decoder layer 2 (no act): N=267, Ktot=1728
    mma_gemm<OUTD, LATENT, IN1, EXPERTS, false, 0><<<gridO, blk>>>(
        z, LATENT, d2, HIDDEN, coef, w2, b2, nullptr, nullptr,
        out, OUTD, nullptr, nullptr, nullptr);
}